// round 10
// baseline (speedup 1.0000x reference)
#include <cuda_runtime.h>
#include <cuda_fp16.h>
#include <cstdint>

// SparseLinear: y[b,m] = sum_{e: dst[e]==m} values[e] * x[b, src[e]] + bias[m]
// B=32. Cost model (calibrated R2/R4/R9): LTS-bound scatter costs
// ~(f32 atomic lane-ops + gather sectors); f16x2 atomics are HALF-RATE, so
// fp32 v4 red (8 lane-ops/edge) + fp16 gather (2 sectors/edge) is the floor
// config. Single fp32 accumulator: no zero/merge overhead, best precision.
// Per edge: 8 lanes, each gathers 8B fp16 (coalesced 64B) and issues one
// red.global.add.v4.f32 (16B). Both scratch arrays L2-resident.

constexpr int NN = 100000;   // input nodes
constexpr int MM = 100000;   // output nodes
constexpr int BB = 32;       // batch == warp width

__device__ __half g_xh[NN * BB];  // x transposed: (N, B) fp16, 6.4MB
__device__ float  g_yt[MM * BB];  // accumulator:  (M, B) fp32, 12.8MB

// x (B, N) fp32 -> g_xh (N, B) fp16, tiled 32x32 transpose + convert
__global__ void transpose_in_h(const float* __restrict__ x) {
    __shared__ float tile[32][33];
    int n0 = blockIdx.x * 32;
    int tx = threadIdx.x, ty = threadIdx.y;
#pragma unroll
    for (int i = 0; i < 32; i += 8) {
        int b = ty + i;
        int n = n0 + tx;
        tile[b][tx] = (n < NN) ? x[b * NN + n] : 0.0f;     // coalesced read
    }
    __syncthreads();
#pragma unroll
    for (int i = 0; i < 32; i += 8) {
        int n = n0 + ty + i;
        if (n < NN) g_xh[n * BB + tx] = __float2half(tile[tx][ty + i]);
    }
}

// yt[m*32 + b] = bias[m], vectorized (one float4 per thread)
__global__ void init_yt(const float* __restrict__ bias) {
    int idx = blockIdx.x * blockDim.x + threadIdx.x;
    if (idx < MM * 8) {
        float b = __ldg(bias + (idx >> 3));
        ((float4*)g_yt)[idx] = make_float4(b, b, b, b);
    }
}

// 8 lanes per edge: lane q in [0,8) handles batch elems [4q, 4q+4).
// Gather: 8B of fp16 per lane (64B/edge, coalesced -> 2 sectors).
// Scatter: one red.global.add.v4.f32 per lane (8 x 16B = 128B fp32).
constexpr int EITER = 4;        // edges per group-thread
constexpr int EPW = 4 * EITER;  // edges per warp = 16

__global__ void scatter_edges_f32red(const int* __restrict__ indices,
                                     const float* __restrict__ vals, int nnz) {
    long long wid = (long long)((blockIdx.x * blockDim.x + threadIdx.x) >> 5);
    int lane = threadIdx.x & 31;
    int g = lane >> 3;        // edge group within warp: 0..3
    int q = lane & 7;         // batch quarter: 0..7
    long long base = wid * EPW;

#pragma unroll
    for (int i = 0; i < EITER; i++) {
        long long e = base + (long long)i * 4 + g;
        if (e >= nnz) break;
        int   s = __ldg(indices + e);         // broadcast within 8-lane group
        int   d = __ldg(indices + nnz + e);
        float v = __ldg(vals + e);
        // 4 halves = 8B per lane, 64B per edge, warp-coalesced
        uint2 X = __ldg((const uint2*)(g_xh + (size_t)s * BB) + q);
        __half2 h01 = *(const __half2*)&X.x;
        __half2 h23 = *(const __half2*)&X.y;
        float2 f01 = __half22float2(h01);
        float2 f23 = __half22float2(h23);
        float* yp = g_yt + (size_t)d * BB + q * 4;  // 16B aligned
        asm volatile("red.global.add.v4.f32 [%0], {%1, %2, %3, %4};"
                     :: "l"(yp), "f"(v * f01.x), "f"(v * f01.y),
                        "f"(v * f23.x), "f"(v * f23.y)
                     : "memory");
    }
}

// g_yt (M, B) -> out (B, M), tiled transpose (bias already folded in)
__global__ void transpose_out(float* __restrict__ out) {
    __shared__ float tile[32][33];
    int m0 = blockIdx.x * 32;
    int tx = threadIdx.x, ty = threadIdx.y;
#pragma unroll
    for (int i = 0; i < 32; i += 8) {
        int m = m0 + ty + i;
        if (m < MM) tile[ty + i][tx] = g_yt[m * BB + tx]; // coalesced read
    }
    __syncthreads();
#pragma unroll
    for (int i = 0; i < 32; i += 8) {
        int b = ty + i;
        int m = m0 + tx;
        if (m < MM) out[b * MM + m] = tile[tx][b];        // coalesced write
    }
}

extern "C" void kernel_launch(void* const* d_in, const int* in_sizes, int n_in,
                              void* d_out, int out_size) {
    const float* x       = (const float*)d_in[0];  // (B, N, 1) f32
    const int*   indices = (const int*)  d_in[1];  // (2, NNZ)  i32
    const float* values  = (const float*)d_in[2];  // (NNZ,)    f32
    const float* bias    = (const float*)d_in[3];  // (M, 1)    f32
    float* out = (float*)d_out;                    // (B, M, 1) f32
    int nnz = in_sizes[2];

    dim3 tb(32, 8);
    transpose_in_h<<<(NN + 31) / 32, tb>>>(x);
    init_yt<<<(MM * 8 + 255) / 256, 256>>>(bias);

    long long warps = ((long long)nnz + EPW - 1) / EPW;
    long long threads = warps * 32;
    int blocks = (int)((threads + 255) / 256);
    scatter_edges_f32red<<<blocks, 256>>>(indices, values, nnz);

    transpose_out<<<(MM + 31) / 32, tb>>>(out);
}

// round 15
// speedup vs baseline: 1.1385x; 1.1385x over previous
#include <cuda_runtime.h>
#include <cuda_fp16.h>
#include <cstdint>

// SparseLinear: y[b,m] = sum_{e: dst[e]==m} values[e] * x[b, src[e]] + bias[m]
// B=32. Scatter is L2 atomic-OP-count bound. Floor config (measured):
//   fp16 accumulators -> output row = 64B -> 4 x red.global.add.noftz.v4.f16x2
//   per edge (16B max red width), fp16 gather (2 sectors/edge).  ~49us.
// fp16 accumulation error contained by 8-way accumulator split (k~4 terms
// each); merge sums all 8 in fp32 + bias. This round: merge kernel vectorized
// (uint4 loads, 8x fewer lane-ops) to cut the 16.5us merge to ~6us.

constexpr int NN = 100000;   // input nodes
constexpr int MM = 100000;   // output nodes  (divisible by 32)
constexpr int BB = 32;       // batch == warp width
constexpr int NACC = 8;      // spatial accumulator split

__device__ __half g_xh[NN * BB];          // x transposed: (N, B) fp16, 6.4MB
__device__ __half g_acc[NACC][MM * BB];   // fp16 accumulators, 8 x 6.4MB

// x (B, N) fp32 -> g_xh (N, B) fp16, tiled 32x32 transpose + convert
__global__ void transpose_in_h(const float* __restrict__ x) {
    __shared__ float tile[32][33];
    int n0 = blockIdx.x * 32;
    int tx = threadIdx.x, ty = threadIdx.y;
#pragma unroll
    for (int i = 0; i < 32; i += 8) {
        int b = ty + i;
        int n = n0 + tx;
        tile[b][tx] = (n < NN) ? x[b * NN + n] : 0.0f;     // coalesced read
    }
    __syncthreads();
#pragma unroll
    for (int i = 0; i < 32; i += 8) {
        int n = n0 + ty + i;
        if (n < NN) g_xh[n * BB + tx] = __float2half(tile[tx][ty + i]);
    }
}

// zero all 8 accumulators (uint4 = 8 halves per thread)
__global__ void zero_acc() {
    size_t i = (size_t)blockIdx.x * blockDim.x + threadIdx.x;
    size_t total = (size_t)NACC * MM * BB / 8;
    if (i < total) ((uint4*)g_acc)[i] = make_uint4(0u, 0u, 0u, 0u);
}

// 4 lanes per edge: lane q in [0,4) handles batch elems [8q, 8q+8).
// 8 edge-subgroups per warp; subgroup g accumulates into g_acc[g].
// Gather: one uint4 (8 halves). Scatter: one red.global.add.noftz.v4.f16x2.
constexpr int EITER = 2;          // iterations per thread
constexpr int EPW = 8 * EITER;    // edges per warp = 16

__global__ void scatter_edges_h8(const int* __restrict__ indices,
                                 const float* __restrict__ vals, int nnz) {
    long long wid = (long long)((blockIdx.x * blockDim.x + threadIdx.x) >> 5);
    int lane = threadIdx.x & 31;
    int g = lane >> 2;        // edge subgroup within warp = accumulator id: 0..7
    int q = lane & 3;         // batch eighth: 0..3
    long long base = wid * EPW;

#pragma unroll
    for (int i = 0; i < EITER; i++) {
        long long e = base + (long long)i * 8 + g;
        if (e >= nnz) break;
        int   s = __ldg(indices + e);         // broadcast within 4-lane group
        int   d = __ldg(indices + nnz + e);
        float v = __ldg(vals + e);
        // 8 halves = 16B per lane, 64B per edge (L2-resident)
        uint4 X = __ldg((const uint4*)(g_xh + (size_t)s * BB) + q);
        const __half2* hx = (const __half2*)&X;
        unsigned int p[4];
#pragma unroll
        for (int j = 0; j < 4; j++) {
            float2 f = __half22float2(hx[j]);   // multiply in fp32
            __half2 h = __floats2half2_rn(v * f.x, v * f.y);
            p[j] = *(const unsigned int*)&h;
        }
        __half* yp = g_acc[g] + (size_t)d * BB + q * 8;   // 16B aligned
        asm volatile("red.global.add.noftz.v4.f16x2 [%0], {%1, %2, %3, %4};"
                     :: "l"(yp), "r"(p[0]), "r"(p[1]), "r"(p[2]), "r"(p[3])
                     : "memory");
    }
}

// out (B, M) = bias[m] + sum_a float(g_acc[a][m, b]), vectorized merge.
// Block = 128 threads, 32 m-rows (MM % 32 == 0: no guards).
// Phase 1: thread (r = t>>2, q = t&3) sums the 8 accumulators for batch
// octet [8q, 8q+8) of row m0+r using uint4 loads (8 halves per load),
// accumulating in fp32, into an fp32 smem tile.
// Phase 2: transposed coalesced write to out (B, M).
__global__ void merge_transpose_out(const float* __restrict__ bias,
                                    float* __restrict__ out) {
    __shared__ float tile[32][33];
    int m0 = blockIdx.x * 32;
    int t = threadIdx.x;

    // Phase 1: accumulate
    {
        int r = t >> 2;          // local m row: 0..31
        int q = t & 3;           // batch octet: 0..3
        int m = m0 + r;
        float f[8];
        float b = __ldg(bias + m);
#pragma unroll
        for (int j = 0; j < 8; j++) f[j] = b;
        size_t off = (size_t)m * BB + q * 8;
#pragma unroll
        for (int a = 0; a < NACC; a++) {
            uint4 X = __ldg((const uint4*)(g_acc[a] + off));
            const __half2* hx = (const __half2*)&X;
#pragma unroll
            for (int j = 0; j < 4; j++) {
                float2 v = __half22float2(hx[j]);
                f[j * 2]     += v.x;
                f[j * 2 + 1] += v.y;
            }
        }
#pragma unroll
        for (int j = 0; j < 8; j++) tile[r][q * 8 + j] = f[j];
    }
    __syncthreads();

    // Phase 2: out[b*MM + m] = tile[m_local][b], coalesced over m
    {
        int tx = t & 31;         // m offset within tile
        int bq = t >> 5;         // batch quarter: 0..3
#pragma unroll
        for (int i = 0; i < 8; i++) {
            int b = bq * 8 + i;
            out[(size_t)b * MM + m0 + tx] = tile[tx][b];  // stride-33, conflict-free
        }
    }
}

extern "C" void kernel_launch(void* const* d_in, const int* in_sizes, int n_in,
                              void* d_out, int out_size) {
    const float* x       = (const float*)d_in[0];  // (B, N, 1) f32
    const int*   indices = (const int*)  d_in[1];  // (2, NNZ)  i32
    const float* values  = (const float*)d_in[2];  // (NNZ,)    f32
    const float* bias    = (const float*)d_in[3];  // (M, 1)    f32
    float* out = (float*)d_out;                    // (B, M, 1) f32
    int nnz = in_sizes[2];

    dim3 tb(32, 8);
    transpose_in_h<<<(NN + 31) / 32, tb>>>(x);

    size_t zero_threads = (size_t)NACC * MM * BB / 8;
    zero_acc<<<(int)((zero_threads + 255) / 256), 256>>>();

    long long warps = ((long long)nnz + EPW - 1) / EPW;
    long long threads = warps * 32;
    int blocks = (int)((threads + 255) / 256);
    scatter_edges_h8<<<blocks, 256>>>(indices, values, nnz);

    merge_transpose_out<<<MM / 32, 128>>>(bias, out);
}